// round 6
// baseline (speedup 1.0000x reference)
#include <cuda_runtime.h>
#include <cuda_fp16.h>
#include <cstdint>

// Problem constants
#define NMB 32          // N*M
#define TLEN 300
#define VJ 25
#define CH 64
#define KT 9
#define NSKEL (NMB*TLEN)          // 9600 skeletons

// -------- scratch --------
__device__ __half g_xg[NMB*VJ*TLEN*CH];            // GCN output (nm,v,t,c), fp16
__device__ __align__(16) uint32_t g_w2[KT*CH*36];  // conv W packed [tap][co][p(ci/2)] half2, padded p->36
__device__ float g_scale[CH];                      // BN fold: gamma/sqrt(var+eps)
__device__ float g_shift[CH];                      // (conv_b - mean)*scale + beta

__device__ __forceinline__ float to_tf32(float v) {
    uint32_t u;
    asm("cvt.rna.tf32.f32 %0, %1;" : "=r"(u) : "f"(v));
    return __uint_as_float(u);
}

__device__ __forceinline__ void cp_async16(void* dst_smem, const void* src) {
    uint32_t d = (uint32_t)__cvta_generic_to_shared(dst_smem);
    asm volatile("cp.async.ca.shared.global [%0], [%1], 16;" :: "r"(d), "l"(src));
}
#define CP_COMMIT() asm volatile("cp.async.commit_group;")
#define CP_WAIT0()  asm volatile("cp.async.wait_group 0;")

__device__ __forceinline__ void mma_tf32(float* d, const uint32_t* a, uint32_t b0, uint32_t b1) {
    asm volatile("mma.sync.aligned.m16n8k8.row.col.f32.tf32.tf32.f32 "
        "{%0,%1,%2,%3}, {%4,%5,%6,%7}, {%8,%9}, {%0,%1,%2,%3};"
        : "+f"(d[0]), "+f"(d[1]), "+f"(d[2]), "+f"(d[3])
        : "r"(a[0]), "r"(a[1]), "r"(a[2]), "r"(a[3]), "r"(b0), "r"(b1));
}

__device__ __forceinline__ void mma_f16(float* d, const uint32_t* a, uint32_t b0, uint32_t b1) {
    asm volatile("mma.sync.aligned.m16n8k16.row.col.f32.f16.f16.f32 "
        "{%0,%1,%2,%3}, {%4,%5,%6,%7}, {%8,%9}, {%0,%1,%2,%3};"
        : "+f"(d[0]), "+f"(d[1]), "+f"(d[2]), "+f"(d[3])
        : "r"(a[0]), "r"(a[1]), "r"(a[2]), "r"(a[3]), "r"(b0), "r"(b1));
}

// ============================ prep ============================
__global__ void prep_kernel(const float* __restrict__ conv_w,
                            const float* __restrict__ conv_b,
                            const float* __restrict__ bn_gamma,
                            const float* __restrict__ bn_beta,
                            const float* __restrict__ bn_mean,
                            const float* __restrict__ bn_var) {
    const int gtid = blockIdx.x * blockDim.x + threadIdx.x;
    const int gstride = gridDim.x * blockDim.x;
    if (gtid < CH) {
        float inv = bn_gamma[gtid] * rsqrtf(bn_var[gtid] + 1e-5f);
        g_scale[gtid] = inv;
        g_shift[gtid] = (conv_b[gtid] - bn_mean[gtid]) * inv + bn_beta[gtid];
    }
    // conv_w (co, ci, k) -> g_w2[k][co][p] = half2(w[2p][co], w[2p+1][co]), p<32; pad 32..35 = 0
    for (int i = gtid; i < KT*CH*36; i += gstride) {
        int k   = i / (CH*36);
        int rem = i - k*(CH*36);
        int co  = rem / 36;
        int p   = rem % 36;
        uint32_t val = 0;
        if (p < 32) {
            float w0 = conv_w[(co*CH + 2*p    )*KT + k];
            float w1 = conv_w[(co*CH + 2*p + 1)*KT + k];
            __half2 h2 = __floats2half2_rn(w0, w1);
            val = *(uint32_t*)&h2;
        }
        g_w2[i] = val;
    }
}

// ============================ GCN (GEMM1 fp16, GEMM2 tf32) ============================
// Block = 4 skeletons (100 rows, padded 112). 256 threads = 8 warps.
// GEMM1: hw = hs(112x64 fp16) @ Ws(64x64 fp16), warps 0-6 one m16 tile each.
// GEMM2: x = Ah(32x32 tf32) @ hw_s(32x64 fp32) per skeleton, 8 warp-tiles.
#define HS_STR 36       // u32 (half2 pairs) per row
#define WS_STR 36       // u32 per co row
#define GSTR_HW 72
#define GSTR_A 36
#define GCN_S 4

__global__ __launch_bounds__(256, 3)
void gcn_kernel(const float* __restrict__ h,
                const float* __restrict__ adj,
                const float* __restrict__ gcn_w,
                const float* __restrict__ gcn_b) {
    extern __shared__ __align__(16) char smraw[];
    uint32_t* hs2 = (uint32_t*)smraw;                          // 112*36 u32
    uint32_t* Ws2 = hs2 + 112*HS_STR;                          // 64*36 u32
    float*    hw  = (float*)(Ws2 + CH*WS_STR);                 // 128*72 fp32
    float*    Ah  = hw + 128*GSTR_HW;                          // 32*36
    float*    gb  = Ah + 32*GSTR_A;                            // 64
    float*    nrm = gb + CH;                                   // 25

    const int tid = threadIdx.x;
    const int g0  = blockIdx.x * GCN_S;
    const float* hbase = h + (long long)g0 * VJ * CH;

    if (tid < VJ) {
        float s = 0.f;
        for (int u = 0; u < VJ; u++) s += adj[tid*VJ + u];
        nrm[tid] = rsqrtf(s);
    }
    // hs2: fp16 k-pair pack, rows >= 100 zero
    for (int i = tid; i < 112*16; i += 256) {
        int r = i >> 4, c4 = (i & 15) * 4;       // 4 floats = 2 half2
        uint2 val = make_uint2(0, 0);
        if (r < 100) {
            float4 v = *(const float4*)&hbase[r*CH + c4];
            __half2 p0 = __floats2half2_rn(v.x, v.y);
            __half2 p1 = __floats2half2_rn(v.z, v.w);
            val = make_uint2(*(uint32_t*)&p0, *(uint32_t*)&p1);
        }
        *(uint2*)&hs2[r*HS_STR + (i & 15)*2] = val;
    }
    // Ws2[co][q] = half2(gcn_w[2q][co], gcn_w[(2q+1)][co]), q<32
    for (int i = tid; i < CH*WS_STR; i += 256) {
        int co = i / WS_STR, q = i % WS_STR;
        uint32_t val = 0;
        if (q < 32) {
            __half2 h2 = __floats2half2_rn(gcn_w[(2*q)*CH + co], gcn_w[(2*q+1)*CH + co]);
            val = *(uint32_t*)&h2;
        }
        Ws2[i] = val;
    }
    // zero hw pad rows (v = 25..31 of each skeleton)
    for (int i = tid; i < GCN_S*7*18; i += 256) {
        int j = i / 18, c4 = (i % 18) * 4;
        int s = j / 7, rr = j % 7;
        *(float4*)&hw[(s*32 + 25 + rr)*GSTR_HW + c4] = make_float4(0,0,0,0);
    }
    if (tid < CH) gb[tid] = gcn_b[tid];
    __syncthreads();

    // Ah (consumed only after the GEMM1->GEMM2 barrier)
    for (int i = tid; i < 32*32; i += 256) {
        int v = i >> 5, u = i & 31;
        Ah[v*GSTR_A + u] = (v < VJ && u < VJ) ? to_tf32(nrm[v]*adj[v*VJ+u]*nrm[u]) : 0.f;
    }

    const int lane = tid & 31, w = tid >> 5;
    const int gID = lane >> 2, tig = lane & 3;

    // ---- GEMM1 (fp16): warps 0-6, m16 tile at rows w*16 ----
    if (w < 7) {
        float acc[8][4];
#pragma unroll
        for (int nb = 0; nb < 8; nb++)
#pragma unroll
            for (int j = 0; j < 4; j++) acc[nb][j] = 0.f;
#pragma unroll
        for (int kk = 0; kk < 4; kk++) {
            int base = (w*16 + gID)*HS_STR + kk*8 + tig;
            uint32_t a[4];
            a[0] = hs2[base];
            a[1] = hs2[base + 8*HS_STR];
            a[2] = hs2[base + 4];
            a[3] = hs2[base + 8*HS_STR + 4];
            const uint32_t* wp = Ws2 + gID*WS_STR + kk*8 + tig;
#pragma unroll
            for (int nb = 0; nb < 8; nb++) {
                uint32_t b0 = wp[nb*8*WS_STR];
                uint32_t b1 = wp[nb*8*WS_STR + 4];
                mma_f16(acc[nb], a, b0, b1);
            }
        }
#pragma unroll
        for (int nb = 0; nb < 8; nb++) {
            int c = nb*8 + tig*2;
#pragma unroll
            for (int rr = 0; rr < 2; rr++) {
                int r = w*16 + gID + rr*8;
                if (r < 100) {
                    int s = r / VJ, vv = r - s*VJ;
                    float2 val = make_float2(to_tf32(acc[nb][rr*2]), to_tf32(acc[nb][rr*2+1]));
                    *(float2*)&hw[(s*32 + vv)*GSTR_HW + c] = val;
                }
            }
        }
    }
    __syncthreads();

    // ---- GEMM2 (tf32): x = Ah @ hw_s. Warp w: skeleton s=w/2, m-tile mt=w&1 ----
    {
        const int s = w >> 1, mt = w & 1;
        float acc[8][4];
#pragma unroll
        for (int nb = 0; nb < 8; nb++)
#pragma unroll
            for (int j = 0; j < 4; j++) acc[nb][j] = 0.f;
#pragma unroll
        for (int kk = 0; kk < 4; kk++) {
            const float* ap = Ah + (mt*16 + gID)*GSTR_A + kk*8 + tig;
            uint32_t a[4];
            a[0] = __float_as_uint(ap[0]);
            a[1] = __float_as_uint(ap[8*GSTR_A]);
            a[2] = __float_as_uint(ap[4]);
            a[3] = __float_as_uint(ap[8*GSTR_A + 4]);
            const float* wp = hw + (s*32 + kk*8 + tig)*GSTR_HW + gID;
#pragma unroll
            for (int nb = 0; nb < 8; nb++) {
                uint32_t b0 = __float_as_uint(wp[nb*8]);
                uint32_t b1 = __float_as_uint(wp[nb*8 + 4*GSTR_HW]);
                mma_tf32(acc[nb], a, b0, b1);
            }
        }
        const int g = g0 + s;
        const int nm = g / TLEN, t = g % TLEN;
#pragma unroll
        for (int nb = 0; nb < 8; nb++) {
            int c = nb*8 + tig*2;
            float2 gbv = *(const float2*)&gb[c];
#pragma unroll
            for (int rr = 0; rr < 2; rr++) {
                int vv = mt*16 + gID + rr*8;
                if (vv < VJ) {
                    float x0 = fmaxf(acc[nb][rr*2]   + gbv.x, 0.f);
                    float x1 = fmaxf(acc[nb][rr*2+1] + gbv.y, 0.f);
                    __half2 h2 = __floats2half2_rn(x0, x1);
                    *(__half2*)&g_xg[((nm*VJ + vv)*TLEN + t)*CH + c] = h2;
                }
            }
        }
    }
}

// ============================ Conv (fp16 MMA m16n8k16) ============================
#define XSTR_H 72          // halves
#define XSTR_U 36          // u32
#define WSTR_U 36          // u32 per co row
#define XROWS 168
#define CONV_THREADS 160

__global__ __launch_bounds__(CONV_THREADS, 3)
void conv_mma_kernel(const float* __restrict__ h, float* __restrict__ out) {
    extern __shared__ __align__(16) char smraw[];
    __half*   xs  = (__half*)smraw;                        // 168*72 halves
    uint32_t* xsu = (uint32_t*)smraw;
    uint32_t* wb  = (uint32_t*)(smraw + XROWS*XSTR_H*2);   // 2 * 64*36 u32

    const int tid  = threadIdx.x;
    const int bid  = blockIdx.x;
    const int slab = bid >> 1;
    const int half = bid & 1;
    const int nm = slab / VJ, v = slab % VJ;
    const int tbase = half * 150;
    const __half* xg = g_xg + (long long)slab * TLEN * CH;

    for (int i = tid; i < XROWS*8; i += CONV_THREADS) {
        int r = i >> 3, c8 = (i & 7) * 8;
        int tg = tbase - 4 + r;
        __half* dst = &xs[r*XSTR_H + c8];
        if (r < 158 && tg >= 0 && tg < TLEN)
            cp_async16(dst, xg + tg*CH + c8);
        else
            *(float4*)dst = make_float4(0,0,0,0);
    }
    for (int i = tid; i < CH*WSTR_U/4; i += CONV_THREADS)
        cp_async16(&wb[i*4], &g_w2[i*4]);
    CP_COMMIT();
    CP_WAIT0();
    __syncthreads();

    const int lane = tid & 31, w = tid >> 5;
    const int gID = lane >> 2, tig = lane & 3;
    const int r0 = w*32 + gID;

    float acc[2][8][4];
#pragma unroll
    for (int mt = 0; mt < 2; mt++)
#pragma unroll
        for (int nb = 0; nb < 8; nb++)
#pragma unroll
            for (int j = 0; j < 4; j++) acc[mt][nb][j] = 0.f;

    for (int k = 0; k < KT; k++) {
        const uint32_t* wcur = wb + (k & 1) * CH*WSTR_U;
        if (k < KT-1) {
            uint32_t* wnext = wb + ((k+1) & 1) * CH*WSTR_U;
            const uint32_t* wsrc = g_w2 + (k+1)*CH*WSTR_U;
            for (int i = tid; i < CH*WSTR_U/4; i += CONV_THREADS)
                cp_async16(&wnext[i*4], &wsrc[i*4]);
            CP_COMMIT();
        }
#pragma unroll
        for (int kk = 0; kk < 4; kk++) {
            int base = (r0 + k)*XSTR_U + kk*8 + tig;
            uint32_t a0[4], a1[4];
            a0[0] = xsu[base];
            a0[1] = xsu[base + 8*XSTR_U];
            a0[2] = xsu[base + 4];
            a0[3] = xsu[base + 8*XSTR_U + 4];
            a1[0] = xsu[base + 16*XSTR_U];
            a1[1] = xsu[base + 24*XSTR_U];
            a1[2] = xsu[base + 16*XSTR_U + 4];
            a1[3] = xsu[base + 24*XSTR_U + 4];
            const uint32_t* wp = wcur + gID*WSTR_U + kk*8 + tig;
#pragma unroll
            for (int nb = 0; nb < 8; nb++) {
                uint32_t b0 = wp[nb*8*WSTR_U];
                uint32_t b1 = wp[nb*8*WSTR_U + 4];
                mma_f16(acc[0][nb], a0, b0, b1);
                mma_f16(acc[1][nb], a1, b0, b1);
            }
        }
        if (k < KT-1) {
            CP_WAIT0();
            __syncthreads();
        }
    }

#pragma unroll
    for (int mt = 0; mt < 2; mt++) {
#pragma unroll
        for (int nb = 0; nb < 8; nb++) {
            int co = nb*8 + tig*2;
            float2 scl = *(const float2*)&g_scale[co];
            float2 sft = *(const float2*)&g_shift[co];
#pragma unroll
            for (int rr = 0; rr < 2; rr++) {
                int tl = w*32 + mt*16 + gID + rr*8;
                if (tl >= 150) continue;
                int t = tbase + tl;
                long long o = (((long long)nm*TLEN + t)*VJ + v)*CH + co;
                float x0 = fmaxf(acc[mt][nb][rr*2]  *scl.x + sft.x, 0.f);
                float x1 = fmaxf(acc[mt][nb][rr*2+1]*scl.y + sft.y, 0.f);
                float2 hv = *(const float2*)&h[o];
                *(float2*)&out[o] = make_float2(x0 + hv.x, x1 + hv.y);
            }
        }
    }
}

// ============================ launch ============================
extern "C" void kernel_launch(void* const* d_in, const int* in_sizes, int n_in,
                              void* d_out, int out_size) {
    const float* h        = (const float*)d_in[0];
    const float* adj      = (const float*)d_in[1];
    const float* gcn_w    = (const float*)d_in[2];
    const float* gcn_b    = (const float*)d_in[3];
    const float* conv_w   = (const float*)d_in[4];
    const float* conv_b   = (const float*)d_in[5];
    const float* bn_gamma = (const float*)d_in[6];
    const float* bn_beta  = (const float*)d_in[7];
    const float* bn_mean  = (const float*)d_in[8];
    const float* bn_var   = (const float*)d_in[9];
    float* out = (float*)d_out;

    const int gcn_smem  = (112*HS_STR + CH*WS_STR)*4
                        + (128*GSTR_HW + 32*GSTR_A + CH + 32)*4;   // 67200 B
    const int conv_smem = XROWS*XSTR_H*2 + 2*CH*WSTR_U*4;          // 42624 B
    cudaFuncSetAttribute(gcn_kernel,      cudaFuncAttributeMaxDynamicSharedMemorySize, gcn_smem);
    cudaFuncSetAttribute(conv_mma_kernel, cudaFuncAttributeMaxDynamicSharedMemorySize, conv_smem);

    prep_kernel<<<64, 256>>>(conv_w, conv_b, bn_gamma, bn_beta, bn_mean, bn_var);
    gcn_kernel<<<NSKEL/GCN_S, 256, gcn_smem>>>(h, adj, gcn_w, gcn_b);
    conv_mma_kernel<<<NMB*VJ*2, CONV_THREADS, conv_smem>>>(h, out);
}

// round 7
// speedup vs baseline: 1.2109x; 1.2109x over previous
#include <cuda_runtime.h>
#include <cuda_fp16.h>
#include <cstdint>

// Problem constants
#define NMB 32          // N*M
#define TLEN 300
#define VJ 25
#define CH 64
#define KT 9
#define NSKEL (NMB*TLEN)          // 9600 skeletons

// -------- scratch --------
__device__ __half g_xg[NMB*VJ*TLEN*CH];            // GCN output (nm,v,t,c), fp16
__device__ __align__(16) uint32_t g_w2[KT*CH*36];  // conv W packed [tap][co][p(ci/2)] half2
__device__ __align__(16) uint32_t g_gw2[CH*36];    // GCN W packed [co][q(ci/2)] half2
__device__ __align__(16) float g_ah[32*36];        // normalized adjacency, tf32, padded
__device__ float g_scale[CH];                      // BN fold: gamma/sqrt(var+eps)
__device__ float g_shift[CH];                      // (conv_b - mean)*scale + beta

__device__ __forceinline__ float to_tf32(float v) {
    uint32_t u;
    asm("cvt.rna.tf32.f32 %0, %1;" : "=r"(u) : "f"(v));
    return __uint_as_float(u);
}

__device__ __forceinline__ void cp_async16(void* dst_smem, const void* src) {
    uint32_t d = (uint32_t)__cvta_generic_to_shared(dst_smem);
    asm volatile("cp.async.ca.shared.global [%0], [%1], 16;" :: "r"(d), "l"(src));
}
#define CP_COMMIT() asm volatile("cp.async.commit_group;")
#define CP_WAIT0()  asm volatile("cp.async.wait_group 0;")

__device__ __forceinline__ void mma_tf32(float* d, const uint32_t* a, uint32_t b0, uint32_t b1) {
    asm volatile("mma.sync.aligned.m16n8k8.row.col.f32.tf32.tf32.f32 "
        "{%0,%1,%2,%3}, {%4,%5,%6,%7}, {%8,%9}, {%0,%1,%2,%3};"
        : "+f"(d[0]), "+f"(d[1]), "+f"(d[2]), "+f"(d[3])
        : "r"(a[0]), "r"(a[1]), "r"(a[2]), "r"(a[3]), "r"(b0), "r"(b1));
}

__device__ __forceinline__ void mma_f16(float* d, const uint32_t* a, uint32_t b0, uint32_t b1) {
    asm volatile("mma.sync.aligned.m16n8k16.row.col.f32.f16.f16.f32 "
        "{%0,%1,%2,%3}, {%4,%5,%6,%7}, {%8,%9}, {%0,%1,%2,%3};"
        : "+f"(d[0]), "+f"(d[1]), "+f"(d[2]), "+f"(d[3])
        : "r"(a[0]), "r"(a[1]), "r"(a[2]), "r"(a[3]), "r"(b0), "r"(b1));
}

// ============================ prep ============================
__global__ void prep_kernel(const float* __restrict__ adj,
                            const float* __restrict__ gcn_w,
                            const float* __restrict__ conv_w,
                            const float* __restrict__ conv_b,
                            const float* __restrict__ bn_gamma,
                            const float* __restrict__ bn_beta,
                            const float* __restrict__ bn_mean,
                            const float* __restrict__ bn_var) {
    const int tid = threadIdx.x;
    const int gtid = blockIdx.x * blockDim.x + tid;
    const int gstride = gridDim.x * blockDim.x;

    if (blockIdx.x == 0) {
        __shared__ float norm[VJ];
        if (tid < VJ) {
            float s = 0.f;
            for (int u = 0; u < VJ; u++) s += adj[tid*VJ + u];
            norm[tid] = rsqrtf(s);
        }
        __syncthreads();
        // g_ah[v][u], tf32, zero-padded to 32x36
        for (int i = tid; i < 32*36; i += blockDim.x) {
            int v = i / 36, u = i % 36;
            g_ah[i] = (v < VJ && u < VJ) ? to_tf32(norm[v]*adj[v*VJ+u]*norm[u]) : 0.f;
        }
        if (tid < CH) {
            float inv = bn_gamma[tid] * rsqrtf(bn_var[tid] + 1e-5f);
            g_scale[tid] = inv;
            g_shift[tid] = (conv_b[tid] - bn_mean[tid]) * inv + bn_beta[tid];
        }
    }
    // GCN weight pack: g_gw2[co][q] = half2(gcn_w[2q][co], gcn_w[2q+1][co]), q<32
    for (int i = gtid; i < CH*36; i += gstride) {
        int co = i / 36, q = i % 36;
        uint32_t val = 0;
        if (q < 32) {
            __half2 h2 = __floats2half2_rn(gcn_w[(2*q)*CH + co], gcn_w[(2*q+1)*CH + co]);
            val = *(uint32_t*)&h2;
        }
        g_gw2[i] = val;
    }
    // conv_w (co, ci, k) -> g_w2[k][co][p] = half2(w[2p][co], w[2p+1][co]), p<32
    for (int i = gtid; i < KT*CH*36; i += gstride) {
        int k   = i / (CH*36);
        int rem = i - k*(CH*36);
        int co  = rem / 36;
        int p   = rem % 36;
        uint32_t val = 0;
        if (p < 32) {
            float w0 = conv_w[(co*CH + 2*p    )*KT + k];
            float w1 = conv_w[(co*CH + 2*p + 1)*KT + k];
            __half2 h2 = __floats2half2_rn(w0, w1);
            val = *(uint32_t*)&h2;
        }
        g_w2[i] = val;
    }
}

// ============================ GCN (GEMM1 fp16, GEMM2 tf32) ============================
// Block = 4 skeletons (100 rows, padded 112). 256 threads = 8 warps.
// All invariant operands (Ws2, Ah, gb) arrive prepacked via cp.async.
#define HS_STR 36       // u32 (half2 pairs) per row
#define WS_STR 36       // u32 per co row
#define GSTR_HW 72
#define GSTR_A 36
#define GCN_S 4

__global__ __launch_bounds__(256, 3)
void gcn_kernel(const float* __restrict__ h,
                const float* __restrict__ gcn_b) {
    extern __shared__ __align__(16) char smraw[];
    uint32_t* hs2 = (uint32_t*)smraw;                          // 112*36 u32
    uint32_t* Ws2 = hs2 + 112*HS_STR;                          // 64*36 u32
    float*    hw  = (float*)(Ws2 + CH*WS_STR);                 // 128*72 fp32
    float*    Ah  = hw + 128*GSTR_HW;                          // 32*36
    float*    gb  = Ah + 32*GSTR_A;                            // 64

    const int tid = threadIdx.x;
    const int g0  = blockIdx.x * GCN_S;
    const float* hbase = h + (long long)g0 * VJ * CH;

    // invariants via cp.async (14.1 KB total)
    for (int i = tid; i < CH*WS_STR/4; i += 256)
        cp_async16(&Ws2[i*4], &g_gw2[i*4]);
    for (int i = tid; i < 32*GSTR_A/4; i += 256)
        cp_async16(&Ah[i*4], &g_ah[i*4]);
    if (tid < 16)
        cp_async16(&gb[tid*4], &gcn_b[tid*4]);
    CP_COMMIT();

    // hs2: fp16 k-pair pack, coalesced; rows >= 100 zero
    for (int i = tid; i < 112*16; i += 256) {
        int r = i >> 4, c4 = (i & 15) * 4;
        uint2 val = make_uint2(0, 0);
        if (r < 100) {
            float4 v = *(const float4*)&hbase[r*CH + c4];
            __half2 p0 = __floats2half2_rn(v.x, v.y);
            __half2 p1 = __floats2half2_rn(v.z, v.w);
            val = make_uint2(*(uint32_t*)&p0, *(uint32_t*)&p1);
        }
        *(uint2*)&hs2[r*HS_STR + (i & 15)*2] = val;
    }
    // zero hw pad rows (v = 25..31 of each skeleton)
    for (int i = tid; i < GCN_S*7*18; i += 256) {
        int j = i / 18, c4 = (i % 18) * 4;
        int s = j / 7, rr = j % 7;
        *(float4*)&hw[(s*32 + 25 + rr)*GSTR_HW + c4] = make_float4(0,0,0,0);
    }
    CP_WAIT0();
    __syncthreads();

    const int lane = tid & 31, w = tid >> 5;
    const int gID = lane >> 2, tig = lane & 3;

    // ---- GEMM1 (fp16): warps 0-6, m16 tile at rows w*16 ----
    if (w < 7) {
        float acc[8][4];
#pragma unroll
        for (int nb = 0; nb < 8; nb++)
#pragma unroll
            for (int j = 0; j < 4; j++) acc[nb][j] = 0.f;
#pragma unroll
        for (int kk = 0; kk < 4; kk++) {
            int base = (w*16 + gID)*HS_STR + kk*8 + tig;
            uint32_t a[4];
            a[0] = hs2[base];
            a[1] = hs2[base + 8*HS_STR];
            a[2] = hs2[base + 4];
            a[3] = hs2[base + 8*HS_STR + 4];
            const uint32_t* wp = Ws2 + gID*WS_STR + kk*8 + tig;
#pragma unroll
            for (int nb = 0; nb < 8; nb++) {
                uint32_t b0 = wp[nb*8*WS_STR];
                uint32_t b1 = wp[nb*8*WS_STR + 4];
                mma_f16(acc[nb], a, b0, b1);
            }
        }
#pragma unroll
        for (int nb = 0; nb < 8; nb++) {
            int c = nb*8 + tig*2;
#pragma unroll
            for (int rr = 0; rr < 2; rr++) {
                int r = w*16 + gID + rr*8;
                if (r < 100) {
                    int s = r / VJ, vv = r - s*VJ;
                    float2 val = make_float2(to_tf32(acc[nb][rr*2]), to_tf32(acc[nb][rr*2+1]));
                    *(float2*)&hw[(s*32 + vv)*GSTR_HW + c] = val;
                }
            }
        }
    }
    __syncthreads();

    // ---- GEMM2 (tf32): x = Ah @ hw_s. Warp w: skeleton s=w/2, m-tile mt=w&1 ----
    {
        const int s = w >> 1, mt = w & 1;
        float acc[8][4];
#pragma unroll
        for (int nb = 0; nb < 8; nb++)
#pragma unroll
            for (int j = 0; j < 4; j++) acc[nb][j] = 0.f;
#pragma unroll
        for (int kk = 0; kk < 4; kk++) {
            const float* ap = Ah + (mt*16 + gID)*GSTR_A + kk*8 + tig;
            uint32_t a[4];
            a[0] = __float_as_uint(ap[0]);
            a[1] = __float_as_uint(ap[8*GSTR_A]);
            a[2] = __float_as_uint(ap[4]);
            a[3] = __float_as_uint(ap[8*GSTR_A + 4]);
            const float* wp = hw + (s*32 + kk*8 + tig)*GSTR_HW + gID;
#pragma unroll
            for (int nb = 0; nb < 8; nb++) {
                uint32_t b0 = __float_as_uint(wp[nb*8]);
                uint32_t b1 = __float_as_uint(wp[nb*8 + 4*GSTR_HW]);
                mma_tf32(acc[nb], a, b0, b1);
            }
        }
        const int g = g0 + s;
        const int nm = g / TLEN, t = g % TLEN;
#pragma unroll
        for (int nb = 0; nb < 8; nb++) {
            int c = nb*8 + tig*2;
            float2 gbv = *(const float2*)&gb[c];
#pragma unroll
            for (int rr = 0; rr < 2; rr++) {
                int vv = mt*16 + gID + rr*8;
                if (vv < VJ) {
                    float x0 = fmaxf(acc[nb][rr*2]   + gbv.x, 0.f);
                    float x1 = fmaxf(acc[nb][rr*2+1] + gbv.y, 0.f);
                    __half2 h2 = __floats2half2_rn(x0, x1);
                    *(__half2*)&g_xg[((nm*VJ + vv)*TLEN + t)*CH + c] = h2;
                }
            }
        }
    }
}

// ============================ Conv (fp16 MMA m16n8k16) — unchanged ============================
#define XSTR_H 72          // halves
#define XSTR_U 36          // u32
#define WSTR_U 36          // u32 per co row
#define XROWS 168
#define CONV_THREADS 160

__global__ __launch_bounds__(CONV_THREADS, 3)
void conv_mma_kernel(const float* __restrict__ h, float* __restrict__ out) {
    extern __shared__ __align__(16) char smraw[];
    __half*   xs  = (__half*)smraw;                        // 168*72 halves
    uint32_t* xsu = (uint32_t*)smraw;
    uint32_t* wb  = (uint32_t*)(smraw + XROWS*XSTR_H*2);   // 2 * 64*36 u32

    const int tid  = threadIdx.x;
    const int bid  = blockIdx.x;
    const int slab = bid >> 1;
    const int half = bid & 1;
    const int nm = slab / VJ, v = slab % VJ;
    const int tbase = half * 150;
    const __half* xg = g_xg + (long long)slab * TLEN * CH;

    for (int i = tid; i < XROWS*8; i += CONV_THREADS) {
        int r = i >> 3, c8 = (i & 7) * 8;
        int tg = tbase - 4 + r;
        __half* dst = &xs[r*XSTR_H + c8];
        if (r < 158 && tg >= 0 && tg < TLEN)
            cp_async16(dst, xg + tg*CH + c8);
        else
            *(float4*)dst = make_float4(0,0,0,0);
    }
    for (int i = tid; i < CH*WSTR_U/4; i += CONV_THREADS)
        cp_async16(&wb[i*4], &g_w2[i*4]);
    CP_COMMIT();
    CP_WAIT0();
    __syncthreads();

    const int lane = tid & 31, w = tid >> 5;
    const int gID = lane >> 2, tig = lane & 3;
    const int r0 = w*32 + gID;

    float acc[2][8][4];
#pragma unroll
    for (int mt = 0; mt < 2; mt++)
#pragma unroll
        for (int nb = 0; nb < 8; nb++)
#pragma unroll
            for (int j = 0; j < 4; j++) acc[mt][nb][j] = 0.f;

    for (int k = 0; k < KT; k++) {
        const uint32_t* wcur = wb + (k & 1) * CH*WSTR_U;
        if (k < KT-1) {
            uint32_t* wnext = wb + ((k+1) & 1) * CH*WSTR_U;
            const uint32_t* wsrc = g_w2 + (k+1)*CH*WSTR_U;
            for (int i = tid; i < CH*WSTR_U/4; i += CONV_THREADS)
                cp_async16(&wnext[i*4], &wsrc[i*4]);
            CP_COMMIT();
        }
#pragma unroll
        for (int kk = 0; kk < 4; kk++) {
            int base = (r0 + k)*XSTR_U + kk*8 + tig;
            uint32_t a0[4], a1[4];
            a0[0] = xsu[base];
            a0[1] = xsu[base + 8*XSTR_U];
            a0[2] = xsu[base + 4];
            a0[3] = xsu[base + 8*XSTR_U + 4];
            a1[0] = xsu[base + 16*XSTR_U];
            a1[1] = xsu[base + 24*XSTR_U];
            a1[2] = xsu[base + 16*XSTR_U + 4];
            a1[3] = xsu[base + 24*XSTR_U + 4];
            const uint32_t* wp = wcur + gID*WSTR_U + kk*8 + tig;
#pragma unroll
            for (int nb = 0; nb < 8; nb++) {
                uint32_t b0 = wp[nb*8*WSTR_U];
                uint32_t b1 = wp[nb*8*WSTR_U + 4];
                mma_f16(acc[0][nb], a0, b0, b1);
                mma_f16(acc[1][nb], a1, b0, b1);
            }
        }
        if (k < KT-1) {
            CP_WAIT0();
            __syncthreads();
        }
    }

#pragma unroll
    for (int mt = 0; mt < 2; mt++) {
#pragma unroll
        for (int nb = 0; nb < 8; nb++) {
            int co = nb*8 + tig*2;
            float2 scl = *(const float2*)&g_scale[co];
            float2 sft = *(const float2*)&g_shift[co];
#pragma unroll
            for (int rr = 0; rr < 2; rr++) {
                int tl = w*32 + mt*16 + gID + rr*8;
                if (tl >= 150) continue;
                int t = tbase + tl;
                long long o = (((long long)nm*TLEN + t)*VJ + v)*CH + co;
                float x0 = fmaxf(acc[mt][nb][rr*2]  *scl.x + sft.x, 0.f);
                float x1 = fmaxf(acc[mt][nb][rr*2+1]*scl.y + sft.y, 0.f);
                float2 hv = *(const float2*)&h[o];
                *(float2*)&out[o] = make_float2(x0 + hv.x, x1 + hv.y);
            }
        }
    }
}

// ============================ launch ============================
extern "C" void kernel_launch(void* const* d_in, const int* in_sizes, int n_in,
                              void* d_out, int out_size) {
    const float* h        = (const float*)d_in[0];
    const float* adj      = (const float*)d_in[1];
    const float* gcn_w    = (const float*)d_in[2];
    const float* gcn_b    = (const float*)d_in[3];
    const float* conv_w   = (const float*)d_in[4];
    const float* conv_b   = (const float*)d_in[5];
    const float* bn_gamma = (const float*)d_in[6];
    const float* bn_beta  = (const float*)d_in[7];
    const float* bn_mean  = (const float*)d_in[8];
    const float* bn_var   = (const float*)d_in[9];
    float* out = (float*)d_out;

    const int gcn_smem  = (112*HS_STR + CH*WS_STR)*4
                        + (128*GSTR_HW + 32*GSTR_A + CH)*4;    // ~67 KB
    const int conv_smem = XROWS*XSTR_H*2 + 2*CH*WSTR_U*4;      // 42624 B
    cudaFuncSetAttribute(gcn_kernel,      cudaFuncAttributeMaxDynamicSharedMemorySize, gcn_smem);
    cudaFuncSetAttribute(conv_mma_kernel, cudaFuncAttributeMaxDynamicSharedMemorySize, conv_smem);

    prep_kernel<<<64, 256>>>(adj, gcn_w, conv_w, conv_b, bn_gamma, bn_beta, bn_mean, bn_var);
    gcn_kernel<<<NSKEL/GCN_S, 256, gcn_smem>>>(h, gcn_b);
    conv_mma_kernel<<<NMB*VJ*2, CONV_THREADS, conv_smem>>>(h, out);
}

// round 8
// speedup vs baseline: 1.2546x; 1.0361x over previous
#include <cuda_runtime.h>
#include <cuda_fp16.h>
#include <cstdint>

// Problem constants
#define NMB 32          // N*M
#define TLEN 300
#define VJ 25
#define CH 64
#define KT 9
#define NSKEL (NMB*TLEN)          // 9600 skeletons

// -------- scratch --------
__device__ __half g_xg[NMB*VJ*TLEN*CH];            // GCN output (nm,v,t,c), fp16
__device__ __align__(16) uint32_t g_w2[KT*CH*36];  // conv W packed [tap][co][p(ci/2)] half2
__device__ __align__(16) uint32_t g_gw2[CH*36];    // GCN W packed [co][q(ci/2)] half2
__device__ __align__(16) float g_ah[32*36];        // normalized adjacency, tf32, padded
__device__ float g_scale[CH];                      // BN fold: gamma/sqrt(var+eps)
__device__ float g_shift[CH];                      // (conv_b - mean)*scale + beta

__device__ __forceinline__ float to_tf32(float v) {
    uint32_t u;
    asm("cvt.rna.tf32.f32 %0, %1;" : "=r"(u) : "f"(v));
    return __uint_as_float(u);
}

__device__ __forceinline__ void cp_async16(void* dst_smem, const void* src) {
    uint32_t d = (uint32_t)__cvta_generic_to_shared(dst_smem);
    asm volatile("cp.async.ca.shared.global [%0], [%1], 16;" :: "r"(d), "l"(src));
}
#define CP_COMMIT() asm volatile("cp.async.commit_group;")
#define CP_WAIT0()  asm volatile("cp.async.wait_group 0;")

__device__ __forceinline__ void mma_tf32(float* d, const uint32_t* a, uint32_t b0, uint32_t b1) {
    asm volatile("mma.sync.aligned.m16n8k8.row.col.f32.tf32.tf32.f32 "
        "{%0,%1,%2,%3}, {%4,%5,%6,%7}, {%8,%9}, {%0,%1,%2,%3};"
        : "+f"(d[0]), "+f"(d[1]), "+f"(d[2]), "+f"(d[3])
        : "r"(a[0]), "r"(a[1]), "r"(a[2]), "r"(a[3]), "r"(b0), "r"(b1));
}

__device__ __forceinline__ void mma_f16(float* d, const uint32_t* a, uint32_t b0, uint32_t b1) {
    asm volatile("mma.sync.aligned.m16n8k16.row.col.f32.f16.f16.f32 "
        "{%0,%1,%2,%3}, {%4,%5,%6,%7}, {%8,%9}, {%0,%1,%2,%3};"
        : "+f"(d[0]), "+f"(d[1]), "+f"(d[2]), "+f"(d[3])
        : "r"(a[0]), "r"(a[1]), "r"(a[2]), "r"(a[3]), "r"(b0), "r"(b1));
}

__device__ __forceinline__ void ldsm_x4(uint32_t* r, uint32_t saddr) {
    asm volatile("ldmatrix.sync.aligned.m8n8.x4.shared.b16 {%0,%1,%2,%3}, [%4];"
        : "=r"(r[0]), "=r"(r[1]), "=r"(r[2]), "=r"(r[3]) : "r"(saddr));
}

// ============================ prep ============================
__global__ void prep_kernel(const float* __restrict__ adj,
                            const float* __restrict__ gcn_w,
                            const float* __restrict__ conv_w,
                            const float* __restrict__ conv_b,
                            const float* __restrict__ bn_gamma,
                            const float* __restrict__ bn_beta,
                            const float* __restrict__ bn_mean,
                            const float* __restrict__ bn_var) {
    const int tid = threadIdx.x;
    const int gtid = blockIdx.x * blockDim.x + tid;
    const int gstride = gridDim.x * blockDim.x;

    if (blockIdx.x == 0) {
        __shared__ float norm[VJ];
        if (tid < VJ) {
            float s = 0.f;
            for (int u = 0; u < VJ; u++) s += adj[tid*VJ + u];
            norm[tid] = rsqrtf(s);
        }
        __syncthreads();
        for (int i = tid; i < 32*36; i += blockDim.x) {
            int v = i / 36, u = i % 36;
            g_ah[i] = (v < VJ && u < VJ) ? to_tf32(norm[v]*adj[v*VJ+u]*norm[u]) : 0.f;
        }
        if (tid < CH) {
            float inv = bn_gamma[tid] * rsqrtf(bn_var[tid] + 1e-5f);
            g_scale[tid] = inv;
            g_shift[tid] = (conv_b[tid] - bn_mean[tid]) * inv + bn_beta[tid];
        }
    }
    for (int i = gtid; i < CH*36; i += gstride) {
        int co = i / 36, q = i % 36;
        uint32_t val = 0;
        if (q < 32) {
            __half2 h2 = __floats2half2_rn(gcn_w[(2*q)*CH + co], gcn_w[(2*q+1)*CH + co]);
            val = *(uint32_t*)&h2;
        }
        g_gw2[i] = val;
    }
    for (int i = gtid; i < KT*CH*36; i += gstride) {
        int k   = i / (CH*36);
        int rem = i - k*(CH*36);
        int co  = rem / 36;
        int p   = rem % 36;
        uint32_t val = 0;
        if (p < 32) {
            float w0 = conv_w[(co*CH + 2*p    )*KT + k];
            float w1 = conv_w[(co*CH + 2*p + 1)*KT + k];
            __half2 h2 = __floats2half2_rn(w0, w1);
            val = *(uint32_t*)&h2;
        }
        g_w2[i] = val;
    }
}

// ============================ GCN (unchanged from R6) ============================
#define HS_STR 36
#define WS_STR 36
#define GSTR_HW 72
#define GSTR_A 36
#define GCN_S 4

__global__ __launch_bounds__(256, 3)
void gcn_kernel(const float* __restrict__ h,
                const float* __restrict__ gcn_b) {
    extern __shared__ __align__(16) char smraw[];
    uint32_t* hs2 = (uint32_t*)smraw;
    uint32_t* Ws2 = hs2 + 112*HS_STR;
    float*    hw  = (float*)(Ws2 + CH*WS_STR);
    float*    Ah  = hw + 128*GSTR_HW;
    float*    gb  = Ah + 32*GSTR_A;

    const int tid = threadIdx.x;
    const int g0  = blockIdx.x * GCN_S;
    const float* hbase = h + (long long)g0 * VJ * CH;

    for (int i = tid; i < CH*WS_STR/4; i += 256)
        cp_async16(&Ws2[i*4], &g_gw2[i*4]);
    for (int i = tid; i < 32*GSTR_A/4; i += 256)
        cp_async16(&Ah[i*4], &g_ah[i*4]);
    if (tid < 16)
        cp_async16(&gb[tid*4], &gcn_b[tid*4]);
    CP_COMMIT();

    for (int i = tid; i < 112*16; i += 256) {
        int r = i >> 4, c4 = (i & 15) * 4;
        uint2 val = make_uint2(0, 0);
        if (r < 100) {
            float4 v = *(const float4*)&hbase[r*CH + c4];
            __half2 p0 = __floats2half2_rn(v.x, v.y);
            __half2 p1 = __floats2half2_rn(v.z, v.w);
            val = make_uint2(*(uint32_t*)&p0, *(uint32_t*)&p1);
        }
        *(uint2*)&hs2[r*HS_STR + (i & 15)*2] = val;
    }
    for (int i = tid; i < GCN_S*7*18; i += 256) {
        int j = i / 18, c4 = (i % 18) * 4;
        int s = j / 7, rr = j % 7;
        *(float4*)&hw[(s*32 + 25 + rr)*GSTR_HW + c4] = make_float4(0,0,0,0);
    }
    CP_WAIT0();
    __syncthreads();

    const int lane = tid & 31, w = tid >> 5;
    const int gID = lane >> 2, tig = lane & 3;

    if (w < 7) {
        float acc[8][4];
#pragma unroll
        for (int nb = 0; nb < 8; nb++)
#pragma unroll
            for (int j = 0; j < 4; j++) acc[nb][j] = 0.f;
#pragma unroll
        for (int kk = 0; kk < 4; kk++) {
            int base = (w*16 + gID)*HS_STR + kk*8 + tig;
            uint32_t a[4];
            a[0] = hs2[base];
            a[1] = hs2[base + 8*HS_STR];
            a[2] = hs2[base + 4];
            a[3] = hs2[base + 8*HS_STR + 4];
            const uint32_t* wp = Ws2 + gID*WS_STR + kk*8 + tig;
#pragma unroll
            for (int nb = 0; nb < 8; nb++) {
                uint32_t b0 = wp[nb*8*WS_STR];
                uint32_t b1 = wp[nb*8*WS_STR + 4];
                mma_f16(acc[nb], a, b0, b1);
            }
        }
#pragma unroll
        for (int nb = 0; nb < 8; nb++) {
            int c = nb*8 + tig*2;
#pragma unroll
            for (int rr = 0; rr < 2; rr++) {
                int r = w*16 + gID + rr*8;
                if (r < 100) {
                    int s = r / VJ, vv = r - s*VJ;
                    float2 val = make_float2(to_tf32(acc[nb][rr*2]), to_tf32(acc[nb][rr*2+1]));
                    *(float2*)&hw[(s*32 + vv)*GSTR_HW + c] = val;
                }
            }
        }
    }
    __syncthreads();

    {
        const int s = w >> 1, mt = w & 1;
        float acc[8][4];
#pragma unroll
        for (int nb = 0; nb < 8; nb++)
#pragma unroll
            for (int j = 0; j < 4; j++) acc[nb][j] = 0.f;
#pragma unroll
        for (int kk = 0; kk < 4; kk++) {
            const float* ap = Ah + (mt*16 + gID)*GSTR_A + kk*8 + tig;
            uint32_t a[4];
            a[0] = __float_as_uint(ap[0]);
            a[1] = __float_as_uint(ap[8*GSTR_A]);
            a[2] = __float_as_uint(ap[4]);
            a[3] = __float_as_uint(ap[8*GSTR_A + 4]);
            const float* wp = hw + (s*32 + kk*8 + tig)*GSTR_HW + gID;
#pragma unroll
            for (int nb = 0; nb < 8; nb++) {
                uint32_t b0 = __float_as_uint(wp[nb*8]);
                uint32_t b1 = __float_as_uint(wp[nb*8 + 4*GSTR_HW]);
                mma_tf32(acc[nb], a, b0, b1);
            }
        }
        const int g = g0 + s;
        const int nm = g / TLEN, t = g % TLEN;
#pragma unroll
        for (int nb = 0; nb < 8; nb++) {
            int c = nb*8 + tig*2;
            float2 gbv = *(const float2*)&gb[c];
#pragma unroll
            for (int rr = 0; rr < 2; rr++) {
                int vv = mt*16 + gID + rr*8;
                if (vv < VJ) {
                    float x0 = fmaxf(acc[nb][rr*2]   + gbv.x, 0.f);
                    float x1 = fmaxf(acc[nb][rr*2+1] + gbv.y, 0.f);
                    __half2 h2 = __floats2half2_rn(x0, x1);
                    *(__half2*)&g_xg[((nm*VJ + vv)*TLEN + t)*CH + c] = h2;
                }
            }
        }
    }
}

// ============================ Conv (fp16 MMA + ldmatrix) ============================
// Block = half a (nm,v) slab (150 t-rows). 160 threads = 5 warps, warp = m32 x n64.
// A and B fragments via ldmatrix.x4 (conflict-free at 144B row stride).
#define XSTR_H 72          // halves per X row
#define WSTR_U 36          // u32 per W co row
#define XROWS 168
#define CONV_THREADS 160

__global__ __launch_bounds__(CONV_THREADS, 3)
void conv_mma_kernel(const float* __restrict__ h, float* __restrict__ out) {
    extern __shared__ __align__(16) char smraw[];
    __half*   xs  = (__half*)smraw;                        // 168*72 halves
    uint32_t* wb  = (uint32_t*)(smraw + XROWS*XSTR_H*2);   // 2 * 64*36 u32

    const int tid  = threadIdx.x;
    const int bid  = blockIdx.x;
    const int slab = bid >> 1;
    const int half = bid & 1;
    const int nm = slab / VJ, v = slab % VJ;
    const int tbase = half * 150;
    const __half* xg = g_xg + (long long)slab * TLEN * CH;

    for (int i = tid; i < XROWS*8; i += CONV_THREADS) {
        int r = i >> 3, c8 = (i & 7) * 8;
        int tg = tbase - 4 + r;
        __half* dst = &xs[r*XSTR_H + c8];
        if (r < 158 && tg >= 0 && tg < TLEN)
            cp_async16(dst, xg + tg*CH + c8);
        else
            *(float4*)dst = make_float4(0,0,0,0);
    }
    for (int i = tid; i < CH*WSTR_U/4; i += CONV_THREADS)
        cp_async16(&wb[i*4], &g_w2[i*4]);
    CP_COMMIT();
    CP_WAIT0();
    __syncthreads();

    const int lane = tid & 31, w = tid >> 5;
    const int gID = lane >> 2, tig = lane & 3;

    // ldmatrix per-lane address components
    const uint32_t xs32 = (uint32_t)__cvta_generic_to_shared(xs);
    const uint32_t wb32 = (uint32_t)__cvta_generic_to_shared(wb);
    // A: lanes 0-7 -> m rows 0-7 (k+0), 8-15 -> m 8-15 (k+0), 16-23 -> m 0-7 (k+8), 24-31 -> m 8-15 (k+8)
    const int xrow = ((lane >> 3) & 1) * 8 + (lane & 7);
    const int xkof = (lane >> 4) * 8;                       // halves
    const uint32_t xbase = xs32 + (uint32_t)(((w*32 + xrow)*XSTR_H + xkof) * 2);
    // B: lanes 0-7 -> co 0-7 (k+0), 8-15 -> co 0-7 (k+8), 16-23 -> co 8-15 (k+0), 24-31 -> co 8-15 (k+8)
    const int bco  = (lane & 7) + ((lane >> 4) << 3);
    const int bkof = ((lane >> 3) & 1) * 4;                 // u32
    const uint32_t bbase = wb32 + (uint32_t)((bco*WSTR_U + bkof) * 4);

    float acc[2][8][4];
#pragma unroll
    for (int mt = 0; mt < 2; mt++)
#pragma unroll
        for (int nb = 0; nb < 8; nb++)
#pragma unroll
            for (int j = 0; j < 4; j++) acc[mt][nb][j] = 0.f;

    for (int k = 0; k < KT; k++) {
        const uint32_t wsel = (uint32_t)((k & 1) * (CH*WSTR_U*4));   // 9216 B
        if (k < KT-1) {
            uint32_t* wnext = wb + ((k+1) & 1) * CH*WSTR_U;
            const uint32_t* wsrc = g_w2 + (k+1)*CH*WSTR_U;
            for (int i = tid; i < CH*WSTR_U/4; i += CONV_THREADS)
                cp_async16(&wnext[i*4], &wsrc[i*4]);
            CP_COMMIT();
        }
        const uint32_t xk = xbase + (uint32_t)(k * (XSTR_H*2));      // +144B per tap
#pragma unroll
        for (int kk = 0; kk < 4; kk++) {
            uint32_t a0[4], a1[4];
            ldsm_x4(a0, xk + kk*32);                         // rows w*32+0..15
            ldsm_x4(a1, xk + 16*(XSTR_H*2) + kk*32);         // rows w*32+16..31
            uint32_t bf[4][4];
#pragma unroll
            for (int p = 0; p < 4; p++)
                ldsm_x4(bf[p], bbase + wsel + p*(16*WSTR_U*4) + kk*32);
#pragma unroll
            for (int nb = 0; nb < 8; nb++) {
                uint32_t b0 = bf[nb >> 1][(nb & 1)*2 + 0];
                uint32_t b1 = bf[nb >> 1][(nb & 1)*2 + 1];
                mma_f16(acc[0][nb], a0, b0, b1);
                mma_f16(acc[1][nb], a1, b0, b1);
            }
        }
        if (k < KT-1) {
            CP_WAIT0();
            __syncthreads();
        }
    }

    // Epilogue: BN fold + ReLU + residual
#pragma unroll
    for (int mt = 0; mt < 2; mt++) {
#pragma unroll
        for (int nb = 0; nb < 8; nb++) {
            int co = nb*8 + tig*2;
            float2 scl = *(const float2*)&g_scale[co];
            float2 sft = *(const float2*)&g_shift[co];
#pragma unroll
            for (int rr = 0; rr < 2; rr++) {
                int tl = w*32 + mt*16 + gID + rr*8;
                if (tl >= 150) continue;
                int t = tbase + tl;
                long long o = (((long long)nm*TLEN + t)*VJ + v)*CH + co;
                float x0 = fmaxf(acc[mt][nb][rr*2]  *scl.x + sft.x, 0.f);
                float x1 = fmaxf(acc[mt][nb][rr*2+1]*scl.y + sft.y, 0.f);
                float2 hv = *(const float2*)&h[o];
                *(float2*)&out[o] = make_float2(x0 + hv.x, x1 + hv.y);
            }
        }
    }
}

// ============================ launch ============================
extern "C" void kernel_launch(void* const* d_in, const int* in_sizes, int n_in,
                              void* d_out, int out_size) {
    const float* h        = (const float*)d_in[0];
    const float* adj      = (const float*)d_in[1];
    const float* gcn_w    = (const float*)d_in[2];
    const float* gcn_b    = (const float*)d_in[3];
    const float* conv_w   = (const float*)d_in[4];
    const float* conv_b   = (const float*)d_in[5];
    const float* bn_gamma = (const float*)d_in[6];
    const float* bn_beta  = (const float*)d_in[7];
    const float* bn_mean  = (const float*)d_in[8];
    const float* bn_var   = (const float*)d_in[9];
    float* out = (float*)d_out;

    const int gcn_smem  = (112*HS_STR + CH*WS_STR)*4
                        + (128*GSTR_HW + 32*GSTR_A + CH)*4;
    const int conv_smem = XROWS*XSTR_H*2 + 2*CH*WSTR_U*4;      // 42624 B
    cudaFuncSetAttribute(gcn_kernel,      cudaFuncAttributeMaxDynamicSharedMemorySize, gcn_smem);
    cudaFuncSetAttribute(conv_mma_kernel, cudaFuncAttributeMaxDynamicSharedMemorySize, conv_smem);

    prep_kernel<<<64, 256>>>(adj, gcn_w, conv_w, conv_b, bn_gamma, bn_beta, bn_mean, bn_var);
    gcn_kernel<<<NSKEL/GCN_S, 256, gcn_smem>>>(h, gcn_b);
    conv_mma_kernel<<<NMB*VJ*2, CONV_THREADS, conv_smem>>>(h, out);
}

// round 10
// speedup vs baseline: 1.2724x; 1.0142x over previous
#include <cuda_runtime.h>
#include <cuda_fp16.h>
#include <cstdint>

// Problem constants
#define NMB 32          // N*M
#define TLEN 300
#define VJ 25
#define CH 64
#define KT 9
#define NSKEL (NMB*TLEN)          // 9600 skeletons

// -------- scratch --------
__device__ __half g_xg[NMB*VJ*TLEN*CH];            // GCN output (nm,v,t,c), fp16
__device__ __align__(16) uint32_t g_w2[KT*CH*36];  // conv W packed [tap][co][p(ci/2)] half2
__device__ __align__(16) uint32_t g_gw2[CH*36];    // GCN W packed [co][q(ci/2)] half2
__device__ __align__(16) float g_ah[32*36];        // normalized adjacency, tf32, padded
__device__ float g_scale[CH];                      // BN fold: gamma/sqrt(var+eps)
__device__ float g_shift[CH];                      // (conv_b - mean)*scale + beta

__device__ __forceinline__ float to_tf32(float v) {
    uint32_t u;
    asm("cvt.rna.tf32.f32 %0, %1;" : "=r"(u) : "f"(v));
    return __uint_as_float(u);
}

__device__ __forceinline__ void cp_async16(void* dst_smem, const void* src) {
    uint32_t d = (uint32_t)__cvta_generic_to_shared(dst_smem);
    asm volatile("cp.async.ca.shared.global [%0], [%1], 16;" :: "r"(d), "l"(src));
}
#define CP_COMMIT() asm volatile("cp.async.commit_group;")
#define CP_WAIT0()  asm volatile("cp.async.wait_group 0;")

__device__ __forceinline__ void mma_tf32(float* d, const uint32_t* a, uint32_t b0, uint32_t b1) {
    asm volatile("mma.sync.aligned.m16n8k8.row.col.f32.tf32.tf32.f32 "
        "{%0,%1,%2,%3}, {%4,%5,%6,%7}, {%8,%9}, {%0,%1,%2,%3};"
        : "+f"(d[0]), "+f"(d[1]), "+f"(d[2]), "+f"(d[3])
        : "r"(a[0]), "r"(a[1]), "r"(a[2]), "r"(a[3]), "r"(b0), "r"(b1));
}

__device__ __forceinline__ void mma_f16(float* d, const uint32_t* a, uint32_t b0, uint32_t b1) {
    asm volatile("mma.sync.aligned.m16n8k16.row.col.f32.f16.f16.f32 "
        "{%0,%1,%2,%3}, {%4,%5,%6,%7}, {%8,%9}, {%0,%1,%2,%3};"
        : "+f"(d[0]), "+f"(d[1]), "+f"(d[2]), "+f"(d[3])
        : "r"(a[0]), "r"(a[1]), "r"(a[2]), "r"(a[3]), "r"(b0), "r"(b1));
}

__device__ __forceinline__ void ldsm_x4(uint32_t* r, uint32_t saddr) {
    asm volatile("ldmatrix.sync.aligned.m8n8.x4.shared.b16 {%0,%1,%2,%3}, [%4];"
        : "=r"(r[0]), "=r"(r[1]), "=r"(r[2]), "=r"(r[3]) : "r"(saddr));
}

// ============================ prep ============================
__global__ void prep_kernel(const float* __restrict__ adj,
                            const float* __restrict__ gcn_w,
                            const float* __restrict__ conv_w,
                            const float* __restrict__ conv_b,
                            const float* __restrict__ bn_gamma,
                            const float* __restrict__ bn_beta,
                            const float* __restrict__ bn_mean,
                            const float* __restrict__ bn_var) {
    const int tid = threadIdx.x;
    const int gtid = blockIdx.x * blockDim.x + tid;
    const int gstride = gridDim.x * blockDim.x;

    if (blockIdx.x == 0) {
        __shared__ float norm[VJ];
        if (tid < VJ) {
            float s = 0.f;
            for (int u = 0; u < VJ; u++) s += adj[tid*VJ + u];
            norm[tid] = rsqrtf(s);
        }
        __syncthreads();
        for (int i = tid; i < 32*36; i += blockDim.x) {
            int v = i / 36, u = i % 36;
            g_ah[i] = (v < VJ && u < VJ) ? to_tf32(norm[v]*adj[v*VJ+u]*norm[u]) : 0.f;
        }
        if (tid < CH) {
            float inv = bn_gamma[tid] * rsqrtf(bn_var[tid] + 1e-5f);
            g_scale[tid] = inv;
            g_shift[tid] = (conv_b[tid] - bn_mean[tid]) * inv + bn_beta[tid];
        }
    }
    for (int i = gtid; i < CH*36; i += gstride) {
        int co = i / 36, q = i % 36;
        uint32_t val = 0;
        if (q < 32) {
            __half2 h2 = __floats2half2_rn(gcn_w[(2*q)*CH + co], gcn_w[(2*q+1)*CH + co]);
            val = *(uint32_t*)&h2;
        }
        g_gw2[i] = val;
    }
    for (int i = gtid; i < KT*CH*36; i += gstride) {
        int k   = i / (CH*36);
        int rem = i - k*(CH*36);
        int co  = rem / 36;
        int p   = rem % 36;
        uint32_t val = 0;
        if (p < 32) {
            float w0 = conv_w[(co*CH + 2*p    )*KT + k];
            float w1 = conv_w[(co*CH + 2*p + 1)*KT + k];
            __half2 h2 = __floats2half2_rn(w0, w1);
            val = *(uint32_t*)&h2;
        }
        g_w2[i] = val;
    }
}

// ============================ GCN (persistent: invariants loaded once) ============================
#define HS_STR 36
#define WS_STR 36
#define GSTR_HW 72
#define GSTR_A 36
#define GCN_S 4
#define GCN_GRID 400
#define GCN_ITERS 6          // 400*6 = 2400 groups = NSKEL/GCN_S

__global__ __launch_bounds__(256, 3)
void gcn_kernel(const float* __restrict__ h,
                const float* __restrict__ gcn_b) {
    extern __shared__ __align__(16) char smraw[];
    uint32_t* hs2 = (uint32_t*)smraw;
    uint32_t* Ws2 = hs2 + 112*HS_STR;
    float*    hw  = (float*)(Ws2 + CH*WS_STR);
    float*    Ah  = hw + 128*GSTR_HW;
    float*    gb  = Ah + 32*GSTR_A;

    const int tid = threadIdx.x;

    // ---- invariants: once per block ----
    for (int i = tid; i < CH*WS_STR/4; i += 256)
        cp_async16(&Ws2[i*4], &g_gw2[i*4]);
    for (int i = tid; i < 32*GSTR_A/4; i += 256)
        cp_async16(&Ah[i*4], &g_ah[i*4]);
    if (tid < 16)
        cp_async16(&gb[tid*4], &gcn_b[tid*4]);
    CP_COMMIT();
    // zero hw pad rows once (GEMM1 never writes v>=25 rows; they stay zero)
    for (int i = tid; i < GCN_S*7*18; i += 256) {
        int j = i / 18, c4 = (i % 18) * 4;
        int s = j / 7, rr = j % 7;
        *(float4*)&hw[(s*32 + 25 + rr)*GSTR_HW + c4] = make_float4(0,0,0,0);
    }
    // zero hs2 pad rows once (rows 100..111)
    for (int i = tid; i < 12*HS_STR; i += 256)
        hs2[100*HS_STR + i] = 0;
    CP_WAIT0();

    const int lane = tid & 31, w = tid >> 5;
    const int gID = lane >> 2, tig = lane & 3;

    for (int it = 0; it < GCN_ITERS; it++) {
        const int g0 = (blockIdx.x + it*GCN_GRID) * GCN_S;
        const float* hbase = h + (long long)g0 * VJ * CH;

        // hs2 fill (valid rows only; pads already zero)
        for (int i = tid; i < 100*16; i += 256) {
            int r = i >> 4, c4 = (i & 15) * 4;
            float4 v = *(const float4*)&hbase[r*CH + c4];
            __half2 p0 = __floats2half2_rn(v.x, v.y);
            __half2 p1 = __floats2half2_rn(v.z, v.w);
            *(uint2*)&hs2[r*HS_STR + (i & 15)*2] = make_uint2(*(uint32_t*)&p0, *(uint32_t*)&p1);
        }
        __syncthreads();

        // ---- GEMM1 (fp16): warps 0-6, m16 tile at rows w*16 ----
        if (w < 7) {
            float acc[8][4];
#pragma unroll
            for (int nb = 0; nb < 8; nb++)
#pragma unroll
                for (int j = 0; j < 4; j++) acc[nb][j] = 0.f;
#pragma unroll
            for (int kk = 0; kk < 4; kk++) {
                int base = (w*16 + gID)*HS_STR + kk*8 + tig;
                uint32_t a[4];
                a[0] = hs2[base];
                a[1] = hs2[base + 8*HS_STR];
                a[2] = hs2[base + 4];
                a[3] = hs2[base + 8*HS_STR + 4];
                const uint32_t* wp = Ws2 + gID*WS_STR + kk*8 + tig;
#pragma unroll
                for (int nb = 0; nb < 8; nb++) {
                    uint32_t b0 = wp[nb*8*WS_STR];
                    uint32_t b1 = wp[nb*8*WS_STR + 4];
                    mma_f16(acc[nb], a, b0, b1);
                }
            }
#pragma unroll
            for (int nb = 0; nb < 8; nb++) {
                int c = nb*8 + tig*2;
#pragma unroll
                for (int rr = 0; rr < 2; rr++) {
                    int r = w*16 + gID + rr*8;
                    if (r < 100) {
                        int s = r / VJ, vv = r - s*VJ;
                        float2 val = make_float2(to_tf32(acc[nb][rr*2]), to_tf32(acc[nb][rr*2+1]));
                        *(float2*)&hw[(s*32 + vv)*GSTR_HW + c] = val;
                    }
                }
            }
        }
        __syncthreads();

        // ---- GEMM2 (tf32): x = Ah @ hw_s ----
        {
            const int s = w >> 1, mt = w & 1;
            float acc[8][4];
#pragma unroll
            for (int nb = 0; nb < 8; nb++)
#pragma unroll
                for (int j = 0; j < 4; j++) acc[nb][j] = 0.f;
#pragma unroll
            for (int kk = 0; kk < 4; kk++) {
                const float* ap = Ah + (mt*16 + gID)*GSTR_A + kk*8 + tig;
                uint32_t a[4];
                a[0] = __float_as_uint(ap[0]);
                a[1] = __float_as_uint(ap[8*GSTR_A]);
                a[2] = __float_as_uint(ap[4]);
                a[3] = __float_as_uint(ap[8*GSTR_A + 4]);
                const float* wp = hw + (s*32 + kk*8 + tig)*GSTR_HW + gID;
#pragma unroll
                for (int nb = 0; nb < 8; nb++) {
                    uint32_t b0 = __float_as_uint(wp[nb*8]);
                    uint32_t b1 = __float_as_uint(wp[nb*8 + 4*GSTR_HW]);
                    mma_tf32(acc[nb], a, b0, b1);
                }
            }
            const int g = g0 + s;
            const int nm = g / TLEN, t = g % TLEN;
#pragma unroll
            for (int nb = 0; nb < 8; nb++) {
                int c = nb*8 + tig*2;
                float2 gbv = *(const float2*)&gb[c];
#pragma unroll
                for (int rr = 0; rr < 2; rr++) {
                    int vv = mt*16 + gID + rr*8;
                    if (vv < VJ) {
                        float x0 = fmaxf(acc[nb][rr*2]   + gbv.x, 0.f);
                        float x1 = fmaxf(acc[nb][rr*2+1] + gbv.y, 0.f);
                        __half2 h2 = __floats2half2_rn(x0, x1);
                        *(__half2*)&g_xg[((nm*VJ + vv)*TLEN + t)*CH + c] = h2;
                    }
                }
            }
        }
        if (it < GCN_ITERS-1)
            __syncthreads();   // hw/hs2 reads done before next iteration overwrites
    }
}

// ============================ Conv (fp16 MMA + ldmatrix) — R8 proven version ============================
#define XSTR_H 72          // halves per X row
#define WSTR_U 36          // u32 per W co row
#define XROWS 168
#define CONV_THREADS 160

__global__ __launch_bounds__(CONV_THREADS, 3)
void conv_mma_kernel(const float* __restrict__ h, float* __restrict__ out) {
    extern __shared__ __align__(16) char smraw[];
    __half*   xs  = (__half*)smraw;                        // 168*72 halves
    uint32_t* wb  = (uint32_t*)(smraw + XROWS*XSTR_H*2);   // 2 * 64*36 u32

    const int tid  = threadIdx.x;
    const int bid  = blockIdx.x;
    const int slab = bid >> 1;
    const int half = bid & 1;
    const int nm = slab / VJ, v = slab % VJ;
    const int tbase = half * 150;
    const __half* xg = g_xg + (long long)slab * TLEN * CH;

    for (int i = tid; i < XROWS*8; i += CONV_THREADS) {
        int r = i >> 3, c8 = (i & 7) * 8;
        int tg = tbase - 4 + r;
        __half* dst = &xs[r*XSTR_H + c8];
        if (r < 158 && tg >= 0 && tg < TLEN)
            cp_async16(dst, xg + tg*CH + c8);
        else
            *(float4*)dst = make_float4(0,0,0,0);
    }
    for (int i = tid; i < CH*WSTR_U/4; i += CONV_THREADS)
        cp_async16(&wb[i*4], &g_w2[i*4]);
    CP_COMMIT();
    CP_WAIT0();
    __syncthreads();

    const int lane = tid & 31, w = tid >> 5;
    const int gID = lane >> 2, tig = lane & 3;

    const uint32_t xs32 = (uint32_t)__cvta_generic_to_shared(xs);
    const uint32_t wb32 = (uint32_t)__cvta_generic_to_shared(wb);
    const int xrow = ((lane >> 3) & 1) * 8 + (lane & 7);
    const int xkof = (lane >> 4) * 8;
    const uint32_t xbase = xs32 + (uint32_t)(((w*32 + xrow)*XSTR_H + xkof) * 2);
    const int bco  = (lane & 7) + ((lane >> 4) << 3);
    const int bkof = ((lane >> 3) & 1) * 4;
    const uint32_t bbase = wb32 + (uint32_t)((bco*WSTR_U + bkof) * 4);

    float acc[2][8][4];
#pragma unroll
    for (int mt = 0; mt < 2; mt++)
#pragma unroll
        for (int nb = 0; nb < 8; nb++)
#pragma unroll
            for (int j = 0; j < 4; j++) acc[mt][nb][j] = 0.f;

    for (int k = 0; k < KT; k++) {
        const uint32_t wsel = (uint32_t)((k & 1) * (CH*WSTR_U*4));
        if (k < KT-1) {
            uint32_t* wnext = wb + ((k+1) & 1) * CH*WSTR_U;
            const uint32_t* wsrc = g_w2 + (k+1)*CH*WSTR_U;
            for (int i = tid; i < CH*WSTR_U/4; i += CONV_THREADS)
                cp_async16(&wnext[i*4], &wsrc[i*4]);
            CP_COMMIT();
        }
        const uint32_t xk = xbase + (uint32_t)(k * (XSTR_H*2));
#pragma unroll
        for (int kk = 0; kk < 4; kk++) {
            uint32_t a0[4], a1[4];
            ldsm_x4(a0, xk + kk*32);
            ldsm_x4(a1, xk + 16*(XSTR_H*2) + kk*32);
            uint32_t bf[4][4];
#pragma unroll
            for (int p = 0; p < 4; p++)
                ldsm_x4(bf[p], bbase + wsel + p*(16*WSTR_U*4) + kk*32);
#pragma unroll
            for (int nb = 0; nb < 8; nb++) {
                uint32_t b0 = bf[nb >> 1][(nb & 1)*2 + 0];
                uint32_t b1 = bf[nb >> 1][(nb & 1)*2 + 1];
                mma_f16(acc[0][nb], a0, b0, b1);
                mma_f16(acc[1][nb], a1, b0, b1);
            }
        }
        if (k < KT-1) {
            CP_WAIT0();
            __syncthreads();
        }
    }

#pragma unroll
    for (int mt = 0; mt < 2; mt++) {
#pragma unroll
        for (int nb = 0; nb < 8; nb++) {
            int co = nb*8 + tig*2;
            float2 scl = *(const float2*)&g_scale[co];
            float2 sft = *(const float2*)&g_shift[co];
#pragma unroll
            for (int rr = 0; rr < 2; rr++) {
                int tl = w*32 + mt*16 + gID + rr*8;
                if (tl >= 150) continue;
                int t = tbase + tl;
                long long o = (((long long)nm*TLEN + t)*VJ + v)*CH + co;
                float x0 = fmaxf(acc[mt][nb][rr*2]  *scl.x + sft.x, 0.f);
                float x1 = fmaxf(acc[mt][nb][rr*2+1]*scl.y + sft.y, 0.f);
                float2 hv = *(const float2*)&h[o];
                *(float2*)&out[o] = make_float2(x0 + hv.x, x1 + hv.y);
            }
        }
    }
}

// ============================ launch ============================
extern "C" void kernel_launch(void* const* d_in, const int* in_sizes, int n_in,
                              void* d_out, int out_size) {
    const float* h        = (const float*)d_in[0];
    const float* adj      = (const float*)d_in[1];
    const float* gcn_w    = (const float*)d_in[2];
    const float* gcn_b    = (const float*)d_in[3];
    const float* conv_w   = (const float*)d_in[4];
    const float* conv_b   = (const float*)d_in[5];
    const float* bn_gamma = (const float*)d_in[6];
    const float* bn_beta  = (const float*)d_in[7];
    const float* bn_mean  = (const float*)d_in[8];
    const float* bn_var   = (const float*)d_in[9];
    float* out = (float*)d_out;

    const int gcn_smem  = (112*HS_STR + CH*WS_STR)*4
                        + (128*GSTR_HW + 32*GSTR_A + CH)*4;
    const int conv_smem = XROWS*XSTR_H*2 + 2*CH*WSTR_U*4;      // 42624 B
    cudaFuncSetAttribute(gcn_kernel,      cudaFuncAttributeMaxDynamicSharedMemorySize, gcn_smem);
    cudaFuncSetAttribute(conv_mma_kernel, cudaFuncAttributeMaxDynamicSharedMemorySize, conv_smem);

    prep_kernel<<<64, 256>>>(adj, gcn_w, conv_w, conv_b, bn_gamma, bn_beta, bn_mean, bn_var);
    gcn_kernel<<<GCN_GRID, 256, gcn_smem>>>(h, gcn_b);
    conv_mma_kernel<<<NMB*VJ*2, CONV_THREADS, conv_smem>>>(h, out);
}

// round 11
// speedup vs baseline: 1.4163x; 1.1131x over previous
#include <cuda_runtime.h>
#include <cuda_fp16.h>
#include <cstdint>

// Problem constants
#define NMB 32          // N*M
#define TLEN 300
#define VJ 25
#define CH 64
#define KT 9
#define NSKEL (NMB*TLEN)          // 9600 skeletons

// -------- scratch --------
__device__ __half g_xg[NMB*VJ*TLEN*CH];            // GCN output (nm,v,t,c), fp16
__device__ __align__(16) uint32_t g_w2[KT*CH*36];  // conv W packed [tap][co][p(ci/2)] half2
__device__ __align__(16) uint32_t g_gw2[CH*36];    // GCN W packed [co][q(ci/2)] half2
__device__ __align__(16) uint32_t g_ah2[32*20];    // normalized adjacency fp16 [v][u-pair], padded
__device__ float g_scale[CH];                      // BN fold: gamma/sqrt(var+eps)
__device__ float g_shift[CH];                      // (conv_b - mean)*scale + beta

__device__ __forceinline__ void cp_async16(void* dst_smem, const void* src) {
    uint32_t d = (uint32_t)__cvta_generic_to_shared(dst_smem);
    asm volatile("cp.async.ca.shared.global [%0], [%1], 16;" :: "r"(d), "l"(src));
}
#define CP_COMMIT() asm volatile("cp.async.commit_group;")
#define CP_WAIT0()  asm volatile("cp.async.wait_group 0;")

__device__ __forceinline__ void mma_f16(float* d, const uint32_t* a, uint32_t b0, uint32_t b1) {
    asm volatile("mma.sync.aligned.m16n8k16.row.col.f32.f16.f16.f32 "
        "{%0,%1,%2,%3}, {%4,%5,%6,%7}, {%8,%9}, {%0,%1,%2,%3};"
        : "+f"(d[0]), "+f"(d[1]), "+f"(d[2]), "+f"(d[3])
        : "r"(a[0]), "r"(a[1]), "r"(a[2]), "r"(a[3]), "r"(b0), "r"(b1));
}

__device__ __forceinline__ void ldsm_x4(uint32_t* r, uint32_t saddr) {
    asm volatile("ldmatrix.sync.aligned.m8n8.x4.shared.b16 {%0,%1,%2,%3}, [%4];"
        : "=r"(r[0]), "=r"(r[1]), "=r"(r[2]), "=r"(r[3]) : "r"(saddr));
}

// ============================ prep ============================
__global__ void prep_kernel(const float* __restrict__ adj,
                            const float* __restrict__ gcn_w,
                            const float* __restrict__ conv_w,
                            const float* __restrict__ conv_b,
                            const float* __restrict__ bn_gamma,
                            const float* __restrict__ bn_beta,
                            const float* __restrict__ bn_mean,
                            const float* __restrict__ bn_var) {
    const int tid = threadIdx.x;
    const int gtid = blockIdx.x * blockDim.x + tid;
    const int gstride = gridDim.x * blockDim.x;

    if (blockIdx.x == 0) {
        __shared__ float norm[VJ];
        if (tid < VJ) {
            float s = 0.f;
            for (int u = 0; u < VJ; u++) s += adj[tid*VJ + u];
            norm[tid] = rsqrtf(s);
        }
        __syncthreads();
        // Ah fp16 pack: g_ah2[v][q] = half2(Ah(v,2q), Ah(v,2q+1)), zero-padded to 32x20
        for (int i = tid; i < 32*20; i += blockDim.x) {
            int v = i / 20, q = i % 20;
            uint32_t val = 0;
            if (v < VJ && q < 16) {
                int u0 = 2*q, u1 = 2*q + 1;
                float a0 = (u0 < VJ) ? norm[v]*adj[v*VJ+u0]*norm[u0] : 0.f;
                float a1 = (u1 < VJ) ? norm[v]*adj[v*VJ+u1]*norm[u1] : 0.f;
                __half2 h2 = __floats2half2_rn(a0, a1);
                val = *(uint32_t*)&h2;
            }
            g_ah2[i] = val;
        }
        if (tid < CH) {
            float inv = bn_gamma[tid] * rsqrtf(bn_var[tid] + 1e-5f);
            g_scale[tid] = inv;
            g_shift[tid] = (conv_b[tid] - bn_mean[tid]) * inv + bn_beta[tid];
        }
    }
    for (int i = gtid; i < CH*36; i += gstride) {
        int co = i / 36, q = i % 36;
        uint32_t val = 0;
        if (q < 32) {
            __half2 h2 = __floats2half2_rn(gcn_w[(2*q)*CH + co], gcn_w[(2*q+1)*CH + co]);
            val = *(uint32_t*)&h2;
        }
        g_gw2[i] = val;
    }
    for (int i = gtid; i < KT*CH*36; i += gstride) {
        int k   = i / (CH*36);
        int rem = i - k*(CH*36);
        int co  = rem / 36;
        int p   = rem % 36;
        uint32_t val = 0;
        if (p < 32) {
            float w0 = conv_w[(co*CH + 2*p    )*KT + k];
            float w1 = conv_w[(co*CH + 2*p + 1)*KT + k];
            __half2 h2 = __floats2half2_rn(w0, w1);
            val = *(uint32_t*)&h2;
        }
        g_w2[i] = val;
    }
}

// ============================ GCN (all-fp16, transposed GEMM1) ============================
// Persistent: 600 blocks x 4 iters. Block = 4 skeletons.
// GEMM1': hwT[c][u] = W^T @ h^T.  A = g_gw2 [c][ci-pairs], B = hs2 [u][ci-pairs] (u padded 32/skel).
//   8 warps: mt = w&3 (c m16 tile), ng = w>>2 (u n64 group). Epilogue packs half2(u,u+1) -> hwT.
// GEMM2: x = Ah @ hw.  A = Ah2 fp16 [v][u-pairs], B = hwT [c][u-pairs]. 8 warps: s=w>>1, mt2=w&1.
#define HS_STR 36       // u32 per hs2 row
#define WS_STR 36       // u32 per Ws2 row
#define HWT_STR 20      // u32 per hwT row (conflict-free: 20*gID+tig bijective mod 32)
#define AH_STR 20
#define GCN_S 4
#define GCN_GRID 600
#define GCN_ITERS 4     // 600*4 = 2400 groups

__global__ __launch_bounds__(256, 4)
void gcn_kernel(const float* __restrict__ h,
                const float* __restrict__ gcn_b) {
    extern __shared__ __align__(16) char smraw[];
    uint32_t* hs2 = (uint32_t*)smraw;                 // 128*36
    uint32_t* Ws2 = hs2 + 128*HS_STR;                 // 64*36
    uint32_t* hwT = Ws2 + CH*WS_STR;                  // 256*20  (4 skel x 64 c rows)
    uint32_t* ah2 = hwT + 256*HWT_STR;                // 32*20
    float*    gb  = (float*)(ah2 + 32*AH_STR);        // 64

    const int tid = threadIdx.x;

    // ---- invariants: once per block ----
    for (int i = tid; i < CH*WS_STR/4; i += 256)
        cp_async16(&Ws2[i*4], &g_gw2[i*4]);
    for (int i = tid; i < 32*AH_STR/4; i += 256)
        cp_async16(&ah2[i*4], &g_ah2[i*4]);
    if (tid < 16)
        cp_async16(&gb[tid*4], &gcn_b[tid*4]);
    CP_COMMIT();
    // zero hs2 pad rows once (vv = 25..31 of each skeleton; stay zero forever)
    for (int i = tid; i < GCN_S*7*HS_STR; i += 256) {
        int j = i / HS_STR, e = i % HS_STR;
        int s = j / 7, rr = j % 7;
        hs2[(s*32 + 25 + rr)*HS_STR + e] = 0;
    }
    CP_WAIT0();

    const int lane = tid & 31, w = tid >> 5;
    const int gID = lane >> 2, tig = lane & 3;

    for (int it = 0; it < GCN_ITERS; it++) {
        const int g0 = (blockIdx.x + it*GCN_GRID) * GCN_S;
        const float* hbase = h + (long long)g0 * VJ * CH;

        // hs2 fill: 100 valid rows -> per-skeleton padded slots s*32+vv
        for (int i = tid; i < 100*16; i += 256) {
            int r = i >> 4, c4 = (i & 15) * 4;
            int s = r / VJ, vv = r - s*VJ;
            float4 v = *(const float4*)&hbase[r*CH + c4];
            __half2 p0 = __floats2half2_rn(v.x, v.y);
            __half2 p1 = __floats2half2_rn(v.z, v.w);
            *(uint2*)&hs2[(s*32 + vv)*HS_STR + (i & 15)*2] =
                make_uint2(*(uint32_t*)&p0, *(uint32_t*)&p1);
        }
        __syncthreads();

        // ---- GEMM1' (fp16): hwT = W^T @ h^T, 8 balanced warps ----
        {
            const int mt = w & 3;        // c tile
            const int ng = w >> 2;       // u group (64 rows)
            float acc[8][4];
#pragma unroll
            for (int nb = 0; nb < 8; nb++)
#pragma unroll
                for (int j = 0; j < 4; j++) acc[nb][j] = 0.f;
#pragma unroll
            for (int kk = 0; kk < 4; kk++) {
                int abase = (mt*16 + gID)*WS_STR + kk*8 + tig;
                uint32_t a[4];
                a[0] = Ws2[abase];
                a[1] = Ws2[abase + 8*WS_STR];
                a[2] = Ws2[abase + 4];
                a[3] = Ws2[abase + 8*WS_STR + 4];
                const uint32_t* bp = hs2 + (ng*64 + gID)*HS_STR + kk*8 + tig;
#pragma unroll
                for (int nb = 0; nb < 8; nb++) {
                    uint32_t b0 = bp[nb*8*HS_STR];
                    uint32_t b1 = bp[nb*8*HS_STR + 4];
                    mma_f16(acc[nb], a, b0, b1);
                }
            }
            // pack half2(u,u+1) -> hwT[s*64 + c][upair]
#pragma unroll
            for (int nb = 0; nb < 8; nb++) {
                int srow = (ng*2 + (nb >> 2)) * 64 + mt*16 + gID;   // + rr*8 below
                int col  = (nb & 3)*4 + tig;
#pragma unroll
                for (int rr = 0; rr < 2; rr++) {
                    __half2 h2 = __floats2half2_rn(acc[nb][rr*2], acc[nb][rr*2+1]);
                    hwT[(srow + rr*8)*HWT_STR + col] = *(uint32_t*)&h2;
                }
            }
        }
        __syncthreads();

        // ---- GEMM2 (fp16): x = Ah @ hw ----
        {
            const int s = w >> 1, mt2 = w & 1;
            float acc[8][4];
#pragma unroll
            for (int nb = 0; nb < 8; nb++)
#pragma unroll
                for (int j = 0; j < 4; j++) acc[nb][j] = 0.f;
#pragma unroll
            for (int kk = 0; kk < 2; kk++) {
                int abase = (mt2*16 + gID)*AH_STR + kk*8 + tig;
                uint32_t a[4];
                a[0] = ah2[abase];
                a[1] = ah2[abase + 8*AH_STR];
                a[2] = ah2[abase + 4];
                a[3] = ah2[abase + 8*AH_STR + 4];
                const uint32_t* bp = hwT + (s*64 + gID)*HWT_STR + kk*8 + tig;
#pragma unroll
                for (int nb = 0; nb < 8; nb++) {
                    uint32_t b0 = bp[nb*8*HWT_STR];
                    uint32_t b1 = bp[nb*8*HWT_STR + 4];
                    mma_f16(acc[nb], a, b0, b1);
                }
            }
            const int g = g0 + s;
            const int nm = g / TLEN, t = g % TLEN;
#pragma unroll
            for (int nb = 0; nb < 8; nb++) {
                int c = nb*8 + tig*2;
                float2 gbv = *(const float2*)&gb[c];
#pragma unroll
                for (int rr = 0; rr < 2; rr++) {
                    int vv = mt2*16 + gID + rr*8;
                    if (vv < VJ) {
                        float x0 = fmaxf(acc[nb][rr*2]   + gbv.x, 0.f);
                        float x1 = fmaxf(acc[nb][rr*2+1] + gbv.y, 0.f);
                        __half2 h2 = __floats2half2_rn(x0, x1);
                        *(__half2*)&g_xg[((nm*VJ + vv)*TLEN + t)*CH + c] = h2;
                    }
                }
            }
        }
        if (it < GCN_ITERS-1)
            __syncthreads();   // hs2/hwT reads done before next iteration overwrites
    }
}

// ============================ Conv (fp16 MMA + ldmatrix) — R8 proven, frozen ============================
#define XSTR_H 72          // halves per X row
#define WSTR_U 36          // u32 per W co row
#define XROWS 168
#define CONV_THREADS 160

__global__ __launch_bounds__(CONV_THREADS, 3)
void conv_mma_kernel(const float* __restrict__ h, float* __restrict__ out) {
    extern __shared__ __align__(16) char smraw[];
    __half*   xs  = (__half*)smraw;                        // 168*72 halves
    uint32_t* wb  = (uint32_t*)(smraw + XROWS*XSTR_H*2);   // 2 * 64*36 u32

    const int tid  = threadIdx.x;
    const int bid  = blockIdx.x;
    const int slab = bid >> 1;
    const int half = bid & 1;
    const int nm = slab / VJ, v = slab % VJ;
    const int tbase = half * 150;
    const __half* xg = g_xg + (long long)slab * TLEN * CH;

    for (int i = tid; i < XROWS*8; i += CONV_THREADS) {
        int r = i >> 3, c8 = (i & 7) * 8;
        int tg = tbase - 4 + r;
        __half* dst = &xs[r*XSTR_H + c8];
        if (r < 158 && tg >= 0 && tg < TLEN)
            cp_async16(dst, xg + tg*CH + c8);
        else
            *(float4*)dst = make_float4(0,0,0,0);
    }
    for (int i = tid; i < CH*WSTR_U/4; i += CONV_THREADS)
        cp_async16(&wb[i*4], &g_w2[i*4]);
    CP_COMMIT();
    CP_WAIT0();
    __syncthreads();

    const int lane = tid & 31, w = tid >> 5;
    const int gID = lane >> 2, tig = lane & 3;

    const uint32_t xs32 = (uint32_t)__cvta_generic_to_shared(xs);
    const uint32_t wb32 = (uint32_t)__cvta_generic_to_shared(wb);
    const int xrow = ((lane >> 3) & 1) * 8 + (lane & 7);
    const int xkof = (lane >> 4) * 8;
    const uint32_t xbase = xs32 + (uint32_t)(((w*32 + xrow)*XSTR_H + xkof) * 2);
    const int bco  = (lane & 7) + ((lane >> 4) << 3);
    const int bkof = ((lane >> 3) & 1) * 4;
    const uint32_t bbase = wb32 + (uint32_t)((bco*WSTR_U + bkof) * 4);

    float acc[2][8][4];
#pragma unroll
    for (int mt = 0; mt < 2; mt++)
#pragma unroll
        for (int nb = 0; nb < 8; nb++)
#pragma unroll
            for (int j = 0; j < 4; j++) acc[mt][nb][j] = 0.f;

    for (int k = 0; k < KT; k++) {
        const uint32_t wsel = (uint32_t)((k & 1) * (CH*WSTR_U*4));
        if (k < KT-1) {
            uint32_t* wnext = wb + ((k+1) & 1) * CH*WSTR_U;
            const uint32_t* wsrc = g_w2 + (k+1)*CH*WSTR_U;
            for (int i = tid; i < CH*WSTR_U/4; i += CONV_THREADS)
                cp_async16(&wnext[i*4], &wsrc[i*4]);
            CP_COMMIT();
        }
        const uint32_t xk = xbase + (uint32_t)(k * (XSTR_H*2));
#pragma unroll
        for (int kk = 0; kk < 4; kk++) {
            uint32_t a0[4], a1[4];
            ldsm_x4(a0, xk + kk*32);
            ldsm_x4(a1, xk + 16*(XSTR_H*2) + kk*32);
            uint32_t bf[4][4];
#pragma unroll
            for (int p = 0; p < 4; p++)
                ldsm_x4(bf[p], bbase + wsel + p*(16*WSTR_U*4) + kk*32);
#pragma unroll
            for (int nb = 0; nb < 8; nb++) {
                uint32_t b0 = bf[nb >> 1][(nb & 1)*2 + 0];
                uint32_t b1 = bf[nb >> 1][(nb & 1)*2 + 1];
                mma_f16(acc[0][nb], a0, b0, b1);
                mma_f16(acc[1][nb], a1, b0, b1);
            }
        }
        if (k < KT-1) {
            CP_WAIT0();
            __syncthreads();
        }
    }

#pragma unroll
    for (int mt = 0; mt < 2; mt++) {
#pragma unroll
        for (int nb = 0; nb < 8; nb++) {
            int co = nb*8 + tig*2;
            float2 scl = *(const float2*)&g_scale[co];
            float2 sft = *(const float2*)&g_shift[co];
#pragma unroll
            for (int rr = 0; rr < 2; rr++) {
                int tl = w*32 + mt*16 + gID + rr*8;
                if (tl >= 150) continue;
                int t = tbase + tl;
                long long o = (((long long)nm*TLEN + t)*VJ + v)*CH + co;
                float x0 = fmaxf(acc[mt][nb][rr*2]  *scl.x + sft.x, 0.f);
                float x1 = fmaxf(acc[mt][nb][rr*2+1]*scl.y + sft.y, 0.f);
                float2 hv = *(const float2*)&h[o];
                *(float2*)&out[o] = make_float2(x0 + hv.x, x1 + hv.y);
            }
        }
    }
}

// ============================ launch ============================
extern "C" void kernel_launch(void* const* d_in, const int* in_sizes, int n_in,
                              void* d_out, int out_size) {
    const float* h        = (const float*)d_in[0];
    const float* adj      = (const float*)d_in[1];
    const float* gcn_w    = (const float*)d_in[2];
    const float* gcn_b    = (const float*)d_in[3];
    const float* conv_w   = (const float*)d_in[4];
    const float* conv_b   = (const float*)d_in[5];
    const float* bn_gamma = (const float*)d_in[6];
    const float* bn_beta  = (const float*)d_in[7];
    const float* bn_mean  = (const float*)d_in[8];
    const float* bn_var   = (const float*)d_in[9];
    float* out = (float*)d_out;

    const int gcn_smem  = (128*HS_STR + CH*WS_STR + 256*HWT_STR + 32*AH_STR)*4 + CH*4;  // ~51 KB
    const int conv_smem = XROWS*XSTR_H*2 + 2*CH*WSTR_U*4;      // 42624 B
    cudaFuncSetAttribute(gcn_kernel,      cudaFuncAttributeMaxDynamicSharedMemorySize, gcn_smem);
    cudaFuncSetAttribute(conv_mma_kernel, cudaFuncAttributeMaxDynamicSharedMemorySize, conv_smem);

    prep_kernel<<<64, 256>>>(adj, gcn_w, conv_w, conv_b, bn_gamma, bn_beta, bn_mean, bn_var);
    gcn_kernel<<<GCN_GRID, 256, gcn_smem>>>(h, gcn_b);
    conv_mma_kernel<<<NMB*VJ*2, CONV_THREADS, conv_smem>>>(h, out);
}